// round 3
// baseline (speedup 1.0000x reference)
#include <cuda_runtime.h>
#include <math.h>

// E=8 A=128 TGT=3 HID=16 OUT=128 B=64 W=128 F=132
struct Params {
  const float *Local, *Remote;
  const float *gWih0,*gWhh0,*gbih0,*gbhh0,*gWih1,*gWhh1,*gbih1,*gbhh1;
  const float *aew1,*aeb1,*aew2,*aeb2,*aeg,*aebt;
  const float *mdw1,*mdb1,*mdw2,*mdb2,*mdg,*mdbt;
  const float *mWih0,*mWhh0,*mbih0,*mbhh0,*mWih1,*mWhh1,*mbih1,*mbhh1;
  float* out;
};

__device__ __align__(16) float g_G[128*128*8];   // gate GRU hidden (pre-softmax) [seq][t][8]
__device__ __align__(16) float g_P[16384*128];   // expert-1 GEMM result
__device__ __align__(16) float g_H[16384*16];    // mixed hidden (pre-BN)
__device__             float g_stats[64];        // [call*32 + (sum16|sumsq16)]
__device__ __align__(16) float g_XW0[8192*48];   // mixer layer0 input projection
__device__ __align__(16) float g_HF[64*16];      // mixer final hidden

#define DEVFN __device__ __forceinline__
DEVFN float sigf(float x){ float e=__expf(-x); return __fdividef(1.f,1.f+e); }
DEVFN float tanhf_(float x){
  x=fminf(fmaxf(x,-15.f),15.f);
  float e=__expf(-2.f*x);
  return (1.f-e)*__fdividef(1.f,1.f+e);
}
DEVFN float eluf(float x){ return x>0.f ? x : (__expf(x)-1.f); }
DEVFN void softmax8(const float* gp, float* om){
  float g[8];
#pragma unroll
  for(int e=0;e<8;e++) g[e]=gp[e];
  float m=g[0];
#pragma unroll
  for(int e=1;e<8;e++) m=fmaxf(m,g[e]);
  float s=0.f;
#pragma unroll
  for(int e=0;e<8;e++){ om[e]=__expf(g[e]-m); s+=om[e]; }
  float inv=__fdividef(1.f,s);
#pragma unroll
  for(int e=0;e<8;e++) om[e]*=inv;
}

// ---------------- K1: gate GRU scan (blocks 0..31) + expert-1 GEMM (32..287) --
__global__ __launch_bounds__(256) void k1_gate_gemm(Params P)
{
  const int bid=blockIdx.x, tid=threadIdx.x;
  if (bid < 32) {
    if (bid==0 && tid>=32 && tid<96) g_stats[tid-32]=0.f;  // fresh stats each replay
    if (tid>=32) return;
    const int s = bid*4 + (tid>>3);        // seq 0..127 (0..63 Local, 64..127 Remote)
    const int j = tid & 7;                 // hidden unit
    const int b = s & 63;
    const float* T = ((s<64)? P.Local : P.Remote) + (size_t)b*128*132 + 128;

    float wxr[3],wxz[3],wxn[3];
#pragma unroll
    for(int k=0;k<3;k++){ wxr[k]=P.gWih0[j*3+k]; wxz[k]=P.gWih0[(8+j)*3+k]; wxn[k]=P.gWih0[(16+j)*3+k]; }
    const float bxr=P.gbih0[j], bxz=P.gbih0[8+j], bxn=P.gbih0[16+j];
    float whr[8],whz[8],whn[8];
#pragma unroll
    for(int k=0;k<8;k++){ whr[k]=P.gWhh0[j*8+k]; whz[k]=P.gWhh0[(8+j)*8+k]; whn[k]=P.gWhh0[(16+j)*8+k]; }
    const float bhr=P.gbhh0[j], bhz=P.gbhh0[8+j], bhn=P.gbhh0[16+j];
    float uir[8],uiz[8],uin[8];
#pragma unroll
    for(int k=0;k<8;k++){ uir[k]=P.gWih1[j*8+k]; uiz[k]=P.gWih1[(8+j)*8+k]; uin[k]=P.gWih1[(16+j)*8+k]; }
    const float bir=P.gbih1[j], biz=P.gbih1[8+j], bin_=P.gbih1[16+j];
    float vhr[8],vhz[8],vhn[8];
#pragma unroll
    for(int k=0;k<8;k++){ vhr[k]=P.gWhh1[j*8+k]; vhz[k]=P.gWhh1[(8+j)*8+k]; vhn[k]=P.gWhh1[(16+j)*8+k]; }
    const float cbr=P.gbhh1[j], cbz=P.gbhh1[8+j], cbn=P.gbhh1[16+j];

    float h1=0.f, h2=0.f;
    float* Gout = g_G + (size_t)s*128*8 + j;
    float x0=T[0], x1=T[1], x2=T[2];
    for (int t=0;t<128;t++){
      float nx0=0.f,nx1=0.f,nx2=0.f;
      if (t<127){ const float* Tn=T+(size_t)(t+1)*132; nx0=Tn[0]; nx1=Tn[1]; nx2=Tn[2]; }
      float ir=fmaf(wxr[2],x2,fmaf(wxr[1],x1,fmaf(wxr[0],x0,bxr)));
      float iz=fmaf(wxz[2],x2,fmaf(wxz[1],x1,fmaf(wxz[0],x0,bxz)));
      float in_=fmaf(wxn[2],x2,fmaf(wxn[1],x1,fmaf(wxn[0],x0,bxn)));
      float hr=bhr,hz=bhz,hn=bhn;
#pragma unroll
      for(int k=0;k<8;k++){
        float a=__shfl_sync(0xffffffffu,h1,k,8);
        hr=fmaf(whr[k],a,hr); hz=fmaf(whz[k],a,hz); hn=fmaf(whn[k],a,hn);
      }
      float r=sigf(ir+hr), z=sigf(iz+hz), n=tanhf_(in_+r*hn);
      h1=fmaf(z,h1-n,n);
      float i2r=bir,i2z=biz,i2n=bin_;
#pragma unroll
      for(int k=0;k<8;k++){
        float a=__shfl_sync(0xffffffffu,h1,k,8);
        i2r=fmaf(uir[k],a,i2r); i2z=fmaf(uiz[k],a,i2z); i2n=fmaf(uin[k],a,i2n);
      }
      float q2r=cbr,q2z=cbz,q2n=cbn;
#pragma unroll
      for(int k=0;k<8;k++){
        float a=__shfl_sync(0xffffffffu,h2,k,8);
        q2r=fmaf(vhr[k],a,q2r); q2z=fmaf(vhz[k],a,q2z); q2n=fmaf(vhn[k],a,q2n);
      }
      float r2=sigf(i2r+q2r), z2=sigf(i2z+q2z), n2=tanhf_(i2n+r2*q2n);
      h2=fmaf(z2,h2-n2,n2);
      Gout[(size_t)t*8]=h2;
      x0=nx0; x1=nx1; x2=nx2;
    }
    return;
  }
  // expert-1 GEMM: 64 rows x 128 cols per block
  {
    const int gb=bid-32, row0=gb*64;
    __shared__ float Xs[64][32];
    __shared__ float Ws[32][128];
    const int cg=tid&31, rg=tid>>5;
    float acc[8][4];
#pragma unroll
    for(int i=0;i<8;i++){acc[i][0]=0;acc[i][1]=0;acc[i][2]=0;acc[i][3]=0;}
    for (int kb=0;kb<128;kb+=32){
      for (int q=tid;q<512;q+=256){
        int r=q>>3, f4=q&7, row=row0+r;
        const float* xp=(row<8192)? (P.Local+(size_t)row*132) : (P.Remote+(size_t)(row-8192)*132);
        *(float4*)&Xs[r][f4*4] = *(const float4*)(xp+kb+f4*4);
      }
      for (int q=tid;q<1024;q+=256){
        int kk=q>>5, c=(q&31)*4, e=c>>4, h0=c&15;
        *(float4*)&Ws[kk][c] = *(const float4*)(P.aew1+(size_t)e*2048+(size_t)(kb+kk)*16+h0);
      }
      __syncthreads();
#pragma unroll
      for (int kk=0;kk<32;kk++){
        float4 w=*(float4*)&Ws[kk][cg*4];
#pragma unroll
        for(int i=0;i<8;i++){
          float x=Xs[rg*8+i][kk];
          acc[i][0]=fmaf(x,w.x,acc[i][0]); acc[i][1]=fmaf(x,w.y,acc[i][1]);
          acc[i][2]=fmaf(x,w.z,acc[i][2]); acc[i][3]=fmaf(x,w.w,acc[i][3]);
        }
      }
      __syncthreads();
    }
#pragma unroll
    for(int i=0;i<8;i++)
      *(float4*)&g_P[(size_t)(row0+rg*8+i)*128+cg*4] =
        make_float4(acc[i][0],acc[i][1],acc[i][2],acc[i][3]);
  }
}

// ---------------- K2: gated mix + BN stats ----------------------------------
__global__ __launch_bounds__(256) void k2_mix(Params P)
{
  const int tid=threadIdx.x;
  const int rowbase=blockIdx.x*128;
  const int call=rowbase>>13;
  const int hh=tid&15;
  float s1=0.f,s2=0.f;
  for (int pass=0;pass<8;pass++){
    const int row=rowbase+pass*16+(tid>>4);
    const int rr=row&8191, bb=rr>>7, w=rr&127;
    const float* gp=g_G+((size_t)(call*64+bb)*128+w)*8;
    float om[8]; softmax8(gp,om);
    const float* pp=g_P+(size_t)row*128+hh;
    float h=0.f;
#pragma unroll
    for(int e=0;e<8;e++) h=fmaf(om[e], pp[e*16]+P.aeb1[e*16+hh], h);
    g_H[(size_t)row*16+hh]=h;
    s1+=h; s2=fmaf(h,h,s2);
  }
  __shared__ float red[256];
  red[tid]=s1; __syncthreads();
  for(int off=128;off>=16;off>>=1){ if(tid<off) red[tid]+=red[tid+off]; __syncthreads(); }
  if(tid<16) atomicAdd(&g_stats[call*32+tid], red[tid]);
  __syncthreads();
  red[tid]=s2; __syncthreads();
  for(int off=128;off>=16;off>>=1){ if(tid<off) red[tid]+=red[tid+off]; __syncthreads(); }
  if(tid<16) atomicAdd(&g_stats[call*32+16+tid], red[tid]);
}

// ---------------- K3: BN+ELU+expert2; Z=ZL+ZR; mixer input proj -------------
__global__ __launch_bounds__(256) void k3_z(Params P)
{
  __shared__ float sw2[2048], sb2[128], sWm[768], sbm[48], sg[16], sbt[16];
  __shared__ float smean[32], srstd[32];
  __shared__ float zbuf[256*17];
  const int tid=threadIdx.x;
  for(int i=tid;i<2048;i+=256) sw2[i]=P.aew2[i];
  for(int i=tid;i<768;i+=256)  sWm[i]=P.mWih0[i];
  if(tid<128) sb2[tid]=P.aeb2[tid];
  if(tid<48)  sbm[tid]=P.mbih0[tid];
  if(tid<16){ sg[tid]=P.aeg[tid]; sbt[tid]=P.aebt[tid]; }
  if(tid<32){
    int c=tid>>4, hh=tid&15;
    float s1=g_stats[c*32+hh], s2=g_stats[c*32+16+hh];
    float m=s1*(1.f/8192.f), v=s2*(1.f/8192.f)-m*m;
    smean[tid]=m; srstd[tid]=rsqrtf(v+1e-5f);
  }
  __syncthreads();
  const int p=blockIdx.x*128+(tid&127);
  const int call=tid>>7;
  const int b=p>>7, w=p&127;
  const int row=call*8192+p;
  const float* gp=g_G+((size_t)(call*64+b)*128+w)*8;
  float om[8]; softmax8(gp,om);
  float a[16];
#pragma unroll
  for(int hh=0;hh<16;hh++){
    float h=g_H[(size_t)row*16+hh];
    a[hh]=eluf(sg[hh]*(h-smean[call*16+hh])*srstd[call*16+hh]+sbt[hh]);
  }
  float z[16];
#pragma unroll
  for(int o=0;o<16;o++) z[o]=0.f;
#pragma unroll
  for(int e=0;e<8;e++){
    float we=om[e];
#pragma unroll
    for(int o=0;o<16;o++){
      float acc=sb2[e*16+o];
#pragma unroll
      for(int hh=0;hh<16;hh++) acc=fmaf(a[hh], sw2[e*256+hh*16+o], acc);
      z[o]=fmaf(we,acc,z[o]);
    }
  }
#pragma unroll
  for(int o=0;o<16;o++) zbuf[tid*17+o]=z[o];
  __syncthreads();
  if(tid<128){
    const int pp=blockIdx.x*128+tid;
    float Z[16];
#pragma unroll
    for(int o=0;o<16;o++) Z[o]=zbuf[tid*17+o]+zbuf[(tid+128)*17+o];
    float* xo=g_XW0+(size_t)pp*48;
#pragma unroll
    for(int i=0;i<48;i++){
      float acc=sbm[i];
#pragma unroll
      for(int o=0;o<16;o++) acc=fmaf(sWm[i*16+o],Z[o],acc);
      xo[i]=acc;
    }
  }
}

// ---------------- K4: mixer GRU scan (2 seqs/warp, 16 lanes/seq) ------------
__global__ __launch_bounds__(32,1) void k4_mgru(Params P)
{
  const int lane=threadIdx.x;
  const int s=blockIdx.x*2+(lane>>4);
  const int j=lane&15;
  float w0r[16],w0z[16],w0n[16];
#pragma unroll
  for(int k=0;k<16;k++){ w0r[k]=P.mWhh0[j*16+k]; w0z[k]=P.mWhh0[(16+j)*16+k]; w0n[k]=P.mWhh0[(32+j)*16+k]; }
  const float b0r=P.mbhh0[j], b0z=P.mbhh0[16+j], b0n=P.mbhh0[32+j];
  float uir[16],uiz[16],uin[16];
#pragma unroll
  for(int k=0;k<16;k++){ uir[k]=P.mWih1[j*16+k]; uiz[k]=P.mWih1[(16+j)*16+k]; uin[k]=P.mWih1[(32+j)*16+k]; }
  const float bir=P.mbih1[j], biz=P.mbih1[16+j], bin_=P.mbih1[32+j];
  float vhr[16],vhz[16],vhn[16];
#pragma unroll
  for(int k=0;k<16;k++){ vhr[k]=P.mWhh1[j*16+k]; vhz[k]=P.mWhh1[(16+j)*16+k]; vhn[k]=P.mWhh1[(32+j)*16+k]; }
  const float cbr=P.mbhh1[j], cbz=P.mbhh1[16+j], cbn=P.mbhh1[32+j];

  float h1=0.f,h2=0.f;
  const float* xp=g_XW0+(size_t)s*128*48;
  float xr=xp[j], xz=xp[16+j], xn=xp[32+j];
  for (int t=0;t<128;t++){
    float nxr=0.f,nxz=0.f,nxn=0.f;
    if(t<127){ const float* q=xp+(size_t)(t+1)*48; nxr=q[j]; nxz=q[16+j]; nxn=q[32+j]; }
    float hr=b0r,hz=b0z,hn=b0n;
#pragma unroll
    for(int k=0;k<16;k++){
      float a=__shfl_sync(0xffffffffu,h1,k,16);
      hr=fmaf(w0r[k],a,hr); hz=fmaf(w0z[k],a,hz); hn=fmaf(w0n[k],a,hn);
    }
    float r=sigf(xr+hr), z=sigf(xz+hz), n=tanhf_(xn+r*hn);
    h1=fmaf(z,h1-n,n);
    float i2r=bir,i2z=biz,i2n=bin_;
#pragma unroll
    for(int k=0;k<16;k++){
      float a=__shfl_sync(0xffffffffu,h1,k,16);
      i2r=fmaf(uir[k],a,i2r); i2z=fmaf(uiz[k],a,i2z); i2n=fmaf(uin[k],a,i2n);
    }
    float q2r=cbr,q2z=cbz,q2n=cbn;
#pragma unroll
    for(int k=0;k<16;k++){
      float a=__shfl_sync(0xffffffffu,h2,k,16);
      q2r=fmaf(vhr[k],a,q2r); q2z=fmaf(vhz[k],a,q2z); q2n=fmaf(vhn[k],a,q2n);
    }
    float r2=sigf(i2r+q2r), z2=sigf(i2z+q2z), n2=tanhf_(i2n+r2*q2n);
    h2=fmaf(z2,h2-n2,n2);
    xr=nxr; xz=nxz; xn=nxn;
  }
  g_HF[s*16+j]=h2;
}

// ---------------- K5: decoder expert (one block) ----------------------------
__global__ __launch_bounds__(1024) void k5_dec(Params P)
{
  __shared__ float om_s[64*8], x_s[64*17], a_s[64*16], ms[16], rs[16];
  const int tid=threadIdx.x;
  const int b=tid>>4, hh=tid&15;
  if (tid<64){
    const float* gp=g_G+((size_t)(64+tid)*128+127)*8;
    float om[8]; softmax8(gp,om);
#pragma unroll
    for(int e=0;e<8;e++) om_s[tid*8+e]=om[e];
    x_s[tid*17+16]=P.Remote[(size_t)tid*128*132+127*132+131];
  }
  x_s[b*17+hh]=g_HF[b*16+hh];
  __syncthreads();
  {
    float h=0.f;
#pragma unroll
    for(int e=0;e<8;e++){
      float acc=P.mdb1[e*16+hh];
#pragma unroll
      for(int i=0;i<17;i++) acc=fmaf(x_s[b*17+i], P.mdw1[e*272+i*16+hh], acc);
      h=fmaf(om_s[b*8+e],acc,h);
    }
    a_s[b*16+hh]=h;
  }
  __syncthreads();
  if (tid<16){
    float s1=0.f,s2=0.f;
    for(int bb=0;bb<64;bb++){ float v=a_s[bb*16+tid]; s1+=v; s2=fmaf(v,v,s2); }
    float m=s1*(1.f/64.f), v=s2*(1.f/64.f)-m*m;
    ms[tid]=m; rs[tid]=rsqrtf(v+1e-5f);
  }
  __syncthreads();
  {
    float h=a_s[b*16+hh];
    a_s[b*16+hh]=eluf(P.mdg[hh]*(h-ms[hh])*rs[hh]+P.mdbt[hh]);
  }
  __syncthreads();
  for (int q=tid;q<8192;q+=1024){
    int bb=q>>7, o=q&127;
    float r=0.f;
#pragma unroll
    for(int e=0;e<8;e++){
      float acc=P.mdb2[e*128+o];
#pragma unroll
      for(int k=0;k<16;k++) acc=fmaf(a_s[bb*16+k], P.mdw2[e*2048+k*128+o], acc);
      r=fmaf(om_s[bb*8+e],acc,r);
    }
    P.out[q]=r;
  }
}

extern "C" void kernel_launch(void* const* d_in, const int* in_sizes, int n_in,
                              void* d_out, int out_size)
{
  Params P;
  const float** f = (const float**)d_in;
  P.Local=f[0]; P.Remote=f[1];
  P.gWih0=f[2]; P.gWhh0=f[3]; P.gbih0=f[4]; P.gbhh0=f[5];
  P.gWih1=f[6]; P.gWhh1=f[7]; P.gbih1=f[8]; P.gbhh1=f[9];
  if (in_sizes[10] == 16384) {
    // signature order: ae, md, m-gru
    P.aew1=f[10]; P.aeb1=f[11]; P.aew2=f[12]; P.aeb2=f[13]; P.aeg=f[14]; P.aebt=f[15];
    P.mdw1=f[16]; P.mdb1=f[17]; P.mdw2=f[18]; P.mdb2=f[19]; P.mdg=f[20]; P.mdbt=f[21];
    P.mWih0=f[22]; P.mWhh0=f[23]; P.mbih0=f[24]; P.mbhh0=f[25];
    P.mWih1=f[26]; P.mWhh1=f[27]; P.mbih1=f[28]; P.mbhh1=f[29];
  } else {
    // dict order: m-gru, ae, md
    P.mWih0=f[10]; P.mWhh0=f[11]; P.mbih0=f[12]; P.mbhh0=f[13];
    P.mWih1=f[14]; P.mWhh1=f[15]; P.mbih1=f[16]; P.mbhh1=f[17];
    P.aew1=f[18]; P.aeb1=f[19]; P.aew2=f[20]; P.aeb2=f[21]; P.aeg=f[22]; P.aebt=f[23];
    P.mdw1=f[24]; P.mdb1=f[25]; P.mdw2=f[26]; P.mdb2=f[27]; P.mdg=f[28]; P.mdbt=f[29];
  }
  P.out=(float*)d_out;

  k1_gate_gemm<<<288,256>>>(P);
  k2_mix<<<128,256>>>(P);
  k3_z<<<64,256>>>(P);
  k4_mgru<<<32,32>>>(P);
  k5_dec<<<1,1024>>>(P);
}